// round 9
// baseline (speedup 1.0000x reference)
#include <cuda_runtime.h>
#include <cuda_bf16.h>
#include <cstdint>

// PrRoIPool2D, separable two-pass, fused x-pass/writeback, 2 barriers.
// Fixed shapes: features [2, 256, 50, 50] f32, rois [256, 5], out [256,256,7,7] f32.
//
// Block = (roi, 32-channel group), 256 threads, 6 blocks/SM.
//  0) All threads derive window bounds from the roi (broadcast LDGs).
//  1) Parallel setup (ONE barrier): 128 threads -> dense wyfull[h][p]
//     (1/area folded, zero outside support); 28 threads -> 4-tap x table.
//  2) y-pass: thread=(x, ch pair); each feature cell read ONCE (chunk-skipped),
//     7 bin accumulators -> ytmp (p-stride 549, ch-stride 17: conflict-managed).
//  3) fused x-pass: thread t -> output elements t, t+256, ... (coalesced STG),
//     each a 4-tap dot over ytmp.

#define PH 7
#define PW 7
#define KW 4
#define CG 32
#define SCALE 0.0625f
#define CHP 17          // ytmp channel stride (odd)
#define PSTR 549        // ytmp p stride; 549 mod 32 = 5 -> banks scatter over p

#define C_   256
#define H_   50
#define W_   50
#define HW_  (H_ * W_)
#define CHW_ (C_ * HW_)

__device__ __forceinline__ float hat_cdf(float t) {
    t = fminf(fmaxf(t, -1.0f), 1.0f);
    return (t < 0.0f) ? 0.5f * (t + 1.0f) * (t + 1.0f)
                      : 0.5f + t - 0.5f * t * t;
}

__global__ void __launch_bounds__(256, 6)
prroi_pool_kernel(const float* __restrict__ feat,
                  const float* __restrict__ rois,
                  float* __restrict__ out)
{
    const int r  = blockIdx.x >> 3;
    const int cg = blockIdx.x & 7;

    __shared__ __align__(16) float s_ytmp[PH * PSTR];   // 15.4 KB
    __shared__ __align__(16) float s_wyfull[16][8];     // [h][p], 1/area folded
    __shared__ __align__(16) float s_wx[PW][KW];
    __shared__ int s_offx[PW];

    const int tid = threadIdx.x;

    // ---- 0: window bounds (uniform per thread, broadcast roi loads) ----
    const float* roi = rois + r * 5;
    const float b0 = roi[0];
    const float x1 = roi[1] * SCALE;
    const float y1 = roi[2] * SCALE;
    const float x2 = roi[3] * SCALE;
    const float y2 = roi[4] * SCALE;
    const float bw = (x2 - x1) * (1.0f / PW);
    const float bh = (y2 - y1) * (1.0f / PH);

    const int hstart = min(max((int)ceilf(y1 - 1.0f), 0), H_ - KW);
    const int wstart = min(max((int)ceilf(x1 - 1.0f), 0), W_ - KW);
    const int hend   = min(max((int)ceilf(y1 + 6.0f * bh - 1.0f), 0), H_ - KW);
    const int wend   = min(max((int)ceilf(x1 + 6.0f * bw - 1.0f), 0), W_ - KW);
    const int wh = hend + KW - hstart;     // <= 15 (block-uniform)
    const int ww = wend + KW - wstart;     // <= 15
    const int base = (int)b0 * CHW_ + cg * (CG * HW_);

    const float area = bw * bh;
    const float inva = (area > 0.0f) ? (1.0f / area) : 0.0f;

    // ---- 1: parallel weight setup, one barrier ----
    if (tid < 128) {                               // dense wyfull[h][p]
        const int h = tid >> 3;
        const int p = tid & 7;
        const float lo = y1 + (float)p * bh;
        const float hi = lo + bh;
        const float hf = (float)(hstart + h);
        float w = (hat_cdf(hi - hf) - hat_cdf(lo - hf)) * inva;
        if (p >= PH || (hstart + h) >= H_) w = 0.0f;
        s_wyfull[h][p] = w;
    } else if (tid < 128 + PW * KW) {              // x table + offsets
        const int z = tid - 128;
        const int q = z >> 2;
        const int k = z & 3;
        const float lo = x1 + (float)q * bw;
        const float hi = lo + bw;
        const int i0 = min(max((int)ceilf(lo - 1.0f), 0), W_ - KW);
        s_wx[q][k] = hat_cdf(hi - (float)(i0 + k)) - hat_cdf(lo - (float)(i0 + k));
        if (k == 0) s_offx[q] = i0 - wstart;
    }
    __syncthreads();

    // ---- 2: y-pass: thread = (x, channel pair), each cell read once ----
    {
        const int lane = tid & 31;
        const int warp = tid >> 5;
        const int x    = lane & 15;                // 0..15
        const int ch0  = warp * 2 + (lane >> 4);   // 0..15 ; +16 partner channel
        if (x < ww) {
            const float* g0 = feat + base + ch0 * HW_ + hstart * W_ + wstart + x;
            const float* g1 = g0 + 16 * HW_;
            float acc0[PH], acc1[PH];
            #pragma unroll
            for (int p = 0; p < PH; p++) { acc0[p] = 0.0f; acc1[p] = 0.0f; }

            #pragma unroll
            for (int c = 0; c < 15; c += 5) {
                if (c < wh) {                      // block-uniform chunk skip
                    float v0[5], v1[5];
                    #pragma unroll
                    for (int j = 0; j < 5; j++) {  // batched predicated loads (MLP 10)
                        const int h = c + j;
                        const bool in = (h < wh);
                        v0[j] = in ? g0[h * W_] : 0.0f;
                        v1[j] = in ? g1[h * W_] : 0.0f;
                    }
                    #pragma unroll
                    for (int j = 0; j < 5; j++) {
                        const int h = c + j;
                        const float4 wa = *reinterpret_cast<const float4*>(&s_wyfull[h][0]);
                        const float4 wb = *reinterpret_cast<const float4*>(&s_wyfull[h][4]);
                        acc0[0] = fmaf(v0[j], wa.x, acc0[0]); acc1[0] = fmaf(v1[j], wa.x, acc1[0]);
                        acc0[1] = fmaf(v0[j], wa.y, acc0[1]); acc1[1] = fmaf(v1[j], wa.y, acc1[1]);
                        acc0[2] = fmaf(v0[j], wa.z, acc0[2]); acc1[2] = fmaf(v1[j], wa.z, acc1[2]);
                        acc0[3] = fmaf(v0[j], wa.w, acc0[3]); acc1[3] = fmaf(v1[j], wa.w, acc1[3]);
                        acc0[4] = fmaf(v0[j], wb.x, acc0[4]); acc1[4] = fmaf(v1[j], wb.x, acc1[4]);
                        acc0[5] = fmaf(v0[j], wb.y, acc0[5]); acc1[5] = fmaf(v1[j], wb.y, acc1[5]);
                        acc0[6] = fmaf(v0[j], wb.z, acc0[6]); acc1[6] = fmaf(v1[j], wb.z, acc1[6]);
                    }
                }
            }
            #pragma unroll
            for (int p = 0; p < PH; p++) {
                s_ytmp[p * PSTR + (ch0)      * CHP + x] = acc0[p];
                s_ytmp[p * PSTR + (ch0 + 16) * CHP + x] = acc1[p];
            }
        }
    }
    __syncthreads();

    // ---- 3: fused x-pass + coalesced writeback ----
    {
        float* o = out + r * (C_ * PH * PW) + cg * (CG * PH * PW);
        #pragma unroll
        for (int i = 0; i < 7; i++) {
            const int idx = tid + i * 256;             // 0..1567
            if (idx < CG * PH * PW) {
                const int ch = idx / (PH * PW);        // const divisors -> mulhi
                const int pq = idx - ch * (PH * PW);
                const int p  = pq / PW;
                const int q  = pq - p * PW;

                const int xo = s_offx[q];
                const float4 wx = *reinterpret_cast<const float4*>(s_wx[q]);
                const float* yt = s_ytmp + p * PSTR + ch * CHP + xo;
                float v = yt[0] * wx.x;
                v = fmaf(yt[1], wx.y, v);
                v = fmaf(yt[2], wx.z, v);
                v = fmaf(yt[3], wx.w, v);
                o[idx] = v;                            // fully coalesced STG.32
            }
        }
    }
}

extern "C" void kernel_launch(void* const* d_in, const int* in_sizes, int n_in,
                              void* d_out, int out_size)
{
    const float* feat = (const float*)d_in[0];
    const float* rois = (const float*)d_in[1];
    float* out = (float*)d_out;

    const int R = in_sizes[1] / 5;       // 256
    prroi_pool_kernel<<<R * (C_ / CG), 256>>>(feat, rois, out);
}

// round 10
// speedup vs baseline: 1.1231x; 1.1231x over previous
#include <cuda_runtime.h>
#include <cuda_bf16.h>
#include <cstdint>

// PrRoIPool2D, separable two-pass. R6 dataflow + parallel 1-barrier setup +
// ww-adaptive y-pass lane layout.
// Fixed shapes: features [2, 256, 50, 50] f32, rois [256, 5], out [256,256,7,7] f32.
//
// Block = (roi, 32-channel group), 256 threads, 6 blocks/SM.
//  1) Parallel setup (ONE barrier): 128 threads -> dense wyfull[h][p]
//     (1/area folded, zero outside support); 28 threads -> 4-tap x table.
//  2) y-pass (block-uniform branch):
//       ww<=8 : lanes = 8 x * 32 ch, 1 channel/thread (half work/thread)
//       ww> 8 : lanes = 16 x * 16 ch-pairs, 2 channels/thread (R6 path)
//     Each feature cell read once; 5-row chunk skipping; -> ytmp[p][ch][x].
//  3) x-pass: warp=p, lane=ch -> s_out (stride 49, conflict-free).
//  4) float4 coalesced writeback.

#define PH 7
#define PW 7
#define KW 4
#define CG 32
#define SCALE 0.0625f
#define YPITCH 17       // odd -> conflict-free lane stride in x-pass

#define C_   256
#define H_   50
#define W_   50
#define HW_  (H_ * W_)
#define CHW_ (C_ * HW_)

__device__ __forceinline__ float hat_cdf(float t) {
    t = fminf(fmaxf(t, -1.0f), 1.0f);
    return (t < 0.0f) ? 0.5f * (t + 1.0f) * (t + 1.0f)
                      : 0.5f + t - 0.5f * t * t;
}

__global__ void __launch_bounds__(256, 6)
prroi_pool_kernel(const float* __restrict__ feat,
                  const float* __restrict__ rois,
                  float* __restrict__ out)
{
    const int r  = blockIdx.x >> 3;
    const int cg = blockIdx.x & 7;

    __shared__ __align__(16) float s_ytmp[PH * CG * YPITCH];   // 15.2 KB
    __shared__ __align__(16) float s_out[CG * PH * PW];        // 6.3 KB
    __shared__ __align__(16) float s_wyfull[16][8];            // [h][p], 1/area folded
    __shared__ __align__(16) float s_wx[PW][KW];
    __shared__ int s_offx[PW];

    const int tid  = threadIdx.x;
    const int lane = tid & 31;
    const int warp = tid >> 5;

    // ---- 0: window bounds (uniform per thread, broadcast roi loads) ----
    const float* roi = rois + r * 5;
    const float b0 = roi[0];
    const float x1 = roi[1] * SCALE;
    const float y1 = roi[2] * SCALE;
    const float x2 = roi[3] * SCALE;
    const float y2 = roi[4] * SCALE;
    const float bw = (x2 - x1) * (1.0f / PW);
    const float bh = (y2 - y1) * (1.0f / PH);

    const int hstart = min(max((int)ceilf(y1 - 1.0f), 0), H_ - KW);
    const int wstart = min(max((int)ceilf(x1 - 1.0f), 0), W_ - KW);
    const int hend   = min(max((int)ceilf(y1 + 6.0f * bh - 1.0f), 0), H_ - KW);
    const int wend   = min(max((int)ceilf(x1 + 6.0f * bw - 1.0f), 0), W_ - KW);
    const int wh = hend + KW - hstart;     // <= 15 (block-uniform)
    const int ww = wend + KW - wstart;     // <= 15
    const int base = (int)b0 * CHW_ + cg * (CG * HW_);

    const float area = bw * bh;
    const float inva = (area > 0.0f) ? (1.0f / area) : 0.0f;

    // ---- 1: parallel weight setup, one barrier ----
    if (tid < 128) {                               // dense wyfull[h][p]
        const int h = tid >> 3;
        const int p = tid & 7;
        const float lo = y1 + (float)p * bh;
        const float hi = lo + bh;
        const float hf = (float)(hstart + h);
        float w = (hat_cdf(hi - hf) - hat_cdf(lo - hf)) * inva;
        if (p >= PH || (hstart + h) >= H_) w = 0.0f;
        s_wyfull[h][p] = w;
    } else if (tid < 128 + PW * KW) {              // x table + offsets
        const int z = tid - 128;
        const int q = z >> 2;
        const int k = z & 3;
        const float lo = x1 + (float)q * bw;
        const float hi = lo + bw;
        const int i0 = min(max((int)ceilf(lo - 1.0f), 0), W_ - KW);
        s_wx[q][k] = hat_cdf(hi - (float)(i0 + k)) - hat_cdf(lo - (float)(i0 + k));
        if (k == 0) s_offx[q] = i0 - wstart;
    }
    __syncthreads();

    // ---- 2: y-pass, ww-adaptive lane layout (block-uniform branch) ----
    if (ww <= 8) {
        // 8 x-lanes * 32 channels, 1 channel per thread
        const int x  = lane & 7;
        const int cs = lane >> 3;                  // 0..3
        const int ch = warp * 4 + cs;              // 0..31
        const bool xin = (x < ww);

        const float* g = feat + base + ch * HW_ + hstart * W_ + wstart + x;
        float acc[PH];
        #pragma unroll
        for (int p = 0; p < PH; p++) acc[p] = 0.0f;

        #pragma unroll
        for (int c = 0; c < 15; c += 5) {
            if (c < wh) {
                float v[5];
                #pragma unroll
                for (int j = 0; j < 5; j++) {
                    const int h = c + j;
                    v[j] = (xin && h < wh) ? g[h * W_] : 0.0f;
                }
                #pragma unroll
                for (int j = 0; j < 5; j++) {
                    const int h = c + j;
                    const float4 wa = *reinterpret_cast<const float4*>(&s_wyfull[h][0]);
                    const float4 wb = *reinterpret_cast<const float4*>(&s_wyfull[h][4]);
                    acc[0] = fmaf(v[j], wa.x, acc[0]);
                    acc[1] = fmaf(v[j], wa.y, acc[1]);
                    acc[2] = fmaf(v[j], wa.z, acc[2]);
                    acc[3] = fmaf(v[j], wa.w, acc[3]);
                    acc[4] = fmaf(v[j], wb.x, acc[4]);
                    acc[5] = fmaf(v[j], wb.y, acc[5]);
                    acc[6] = fmaf(v[j], wb.z, acc[6]);
                }
            }
        }
        if (xin) {
            #pragma unroll
            for (int p = 0; p < PH; p++)
                s_ytmp[(p * CG + ch) * YPITCH + x] = acc[p];
        }
    } else {
        // 16 x-lanes * 16 channel-pairs, 2 channels per thread (R6 path)
        const int x   = lane & 15;
        const int ch0 = warp * 2 + (lane >> 4);    // 0..15 ; +16 partner
        if (x < ww) {
            const float* g0 = feat + base + ch0 * HW_ + hstart * W_ + wstart + x;
            const float* g1 = g0 + 16 * HW_;
            float acc0[PH], acc1[PH];
            #pragma unroll
            for (int p = 0; p < PH; p++) { acc0[p] = 0.0f; acc1[p] = 0.0f; }

            #pragma unroll
            for (int c = 0; c < 15; c += 5) {
                if (c < wh) {
                    float v0[5], v1[5];
                    #pragma unroll
                    for (int j = 0; j < 5; j++) {
                        const int h = c + j;
                        const bool in = (h < wh);
                        v0[j] = in ? g0[h * W_] : 0.0f;
                        v1[j] = in ? g1[h * W_] : 0.0f;
                    }
                    #pragma unroll
                    for (int j = 0; j < 5; j++) {
                        const int h = c + j;
                        const float4 wa = *reinterpret_cast<const float4*>(&s_wyfull[h][0]);
                        const float4 wb = *reinterpret_cast<const float4*>(&s_wyfull[h][4]);
                        acc0[0] = fmaf(v0[j], wa.x, acc0[0]); acc1[0] = fmaf(v1[j], wa.x, acc1[0]);
                        acc0[1] = fmaf(v0[j], wa.y, acc0[1]); acc1[1] = fmaf(v1[j], wa.y, acc1[1]);
                        acc0[2] = fmaf(v0[j], wa.z, acc0[2]); acc1[2] = fmaf(v1[j], wa.z, acc1[2]);
                        acc0[3] = fmaf(v0[j], wa.w, acc0[3]); acc1[3] = fmaf(v1[j], wa.w, acc1[3]);
                        acc0[4] = fmaf(v0[j], wb.x, acc0[4]); acc1[4] = fmaf(v1[j], wb.x, acc1[4]);
                        acc0[5] = fmaf(v0[j], wb.y, acc0[5]); acc1[5] = fmaf(v1[j], wb.y, acc1[5]);
                        acc0[6] = fmaf(v0[j], wb.z, acc0[6]); acc1[6] = fmaf(v1[j], wb.z, acc1[6]);
                    }
                }
            }
            #pragma unroll
            for (int p = 0; p < PH; p++) {
                s_ytmp[(p * CG + ch0)      * YPITCH + x] = acc0[p];
                s_ytmp[(p * CG + ch0 + 16) * YPITCH + x] = acc1[p];
            }
        }
    }
    __syncthreads();

    // ---- 3: x-pass: warp = p, lane = ch ----
    if (warp < PH) {
        const float* yt = s_ytmp + (warp * CG + lane) * YPITCH;
        float* so = s_out + lane * (PH * PW) + warp * PW;
        #pragma unroll
        for (int q = 0; q < PW; q++) {
            const int xo = s_offx[q];
            const float4 wx = *reinterpret_cast<const float4*>(s_wx[q]);
            float v = yt[xo] * wx.x;
            v = fmaf(yt[xo + 1], wx.y, v);
            v = fmaf(yt[xo + 2], wx.z, v);
            v = fmaf(yt[xo + 3], wx.w, v);
            so[q] = v;                             // lane stride 49: conflict-free
        }
    }
    __syncthreads();

    // ---- 4: float4 coalesced writeback ----
    {
        float4* o4 = reinterpret_cast<float4*>(out + r * (C_ * PH * PW) + cg * (CG * PH * PW));
        const float4* s4 = reinterpret_cast<const float4*>(s_out);
        #pragma unroll
        for (int i = tid; i < (CG * PH * PW) / 4; i += 256)   // 392 float4s
            o4[i] = s4[i];
    }
}

extern "C" void kernel_launch(void* const* d_in, const int* in_sizes, int n_in,
                              void* d_out, int out_size)
{
    const float* feat = (const float*)d_in[0];
    const float* rois = (const float*)d_in[1];
    float* out = (float*)d_out;

    const int R = in_sizes[1] / 5;       // 256
    prroi_pool_kernel<<<R * (C_ / CG), 256>>>(feat, rois, out);
}